// round 14
// baseline (speedup 1.0000x reference)
#include <cuda_runtime.h>
#include <cuda_bf16.h>
#include <stdint.h>

constexpr int B    = 4;
constexpr int H    = 8;
constexpr int LQ   = 1024;
constexpr int DH   = 64;
constexpr int KLEN = 1024;
constexpr int TBL  = 33;     // 2*MAX_REL_POS + 1
constexpr int PS   = 34;     // S2 j-stride
constexpr int G    = 2;      // qpos per block

__device__ __forceinline__ void ffma2(unsigned long long& acc,
                                      unsigned long long a,
                                      unsigned long long b)
{
    asm("fma.rn.f32x2 %0, %1, %2, %0;" : "+l"(acc) : "l"(a), "l"(b));
}
__device__ __forceinline__ float f2lo(unsigned long long v) {
    return __uint_as_float((unsigned)v);
}
__device__ __forceinline__ float f2hi(unsigned long long v) {
    return __uint_as_float((unsigned)(v >> 32));
}

// ---------------------------------------------------------------------------
// Fused, ZERO-STAGING kernel. One block per TWO consecutive (b,q).
//  * S-compute: thread -> (h = lane>>2, j = warp*4 + lane&3). q-row and
//    table-row read DIRECTLY via LDG (table goes L1-resident; q read once).
//    No smem staging, no staging barriers; smem = 2.2 KB (S2 only).
//  * Gather: idx from int4 time_ids in registers; warp-uniform fast path.
//  * 16 coalesced streaming STG.128 per thread (2 qpos x 8 h).
// ---------------------------------------------------------------------------
__global__ __launch_bounds__(256, 6)
void relpe_fused(const float* __restrict__ q,
                 const float* __restrict__ table,
                 const int* __restrict__ tids,
                 float* __restrict__ out)
{
    __shared__ float S2[G * H * PS + 2];   // [g][h][j], 2.2 KB

    const int blk = blockIdx.x;          // 0 .. B*LQ/G - 1
    const int b   = blk >> 9;            // 512 blocks per batch
    const int q0  = (blk & 511) * G;
    const int tid = threadIdx.x;
    const int lane = tid & 31;
    const int w    = tid >> 5;
    const int h    = lane >> 2;          // 0..7
    const int jj   = w * 4 + (lane & 3); // 0..31

    // ---- time ids: window once, tq per g ----
    int4 t4i = reinterpret_cast<const int4*>(tids + (size_t)b * KLEN)[tid];
    const int tqa = tids[b * KLEN + q0];
    const int tqb = tids[b * KLEN + q0 + 1];

    // ---- S compute: direct-LDG dots (no staging) ----
    {
        const ulonglong2* t2 = reinterpret_cast<const ulonglong2*>(
            table + jj * DH);
        #pragma unroll
        for (int g = 0; g < G; g++) {
            const ulonglong2* q2 = reinterpret_cast<const ulonglong2*>(
                q + (((size_t)b * H + h) * LQ + q0 + g) * DH);
            unsigned long long a0 = 0ull, a1 = 0ull;
            #pragma unroll 8
            for (int c = 0; c < 16; c++) {
                ulonglong2 qa = q2[c];
                ulonglong2 ta = t2[c];
                ffma2(a0, qa.x, ta.x);
                ffma2(a1, qa.y, ta.y);
            }
            S2[(g * H + h) * PS + jj] =
                (f2lo(a0) + f2hi(a0)) + (f2lo(a1) + f2hi(a1));
        }
        // tail j = 32: threads 0..15 -> (g = tid>>3, h = tid&7)
        if (tid < G * H) {
            int g = tid >> 3, h2 = tid & 7;
            const ulonglong2* t3 = reinterpret_cast<const ulonglong2*>(
                table + 32 * DH);
            const ulonglong2* q3 = reinterpret_cast<const ulonglong2*>(
                q + (((size_t)b * H + h2) * LQ + q0 + g) * DH);
            unsigned long long b0 = 0ull, b1 = 0ull;
            #pragma unroll 8
            for (int c = 0; c < 16; c++) {
                ulonglong2 qa = q3[c];
                ulonglong2 ta = t3[c];
                ffma2(b0, qa.x, ta.x);
                ffma2(b1, qa.y, ta.y);
            }
            S2[(g * H + h2) * PS + 32] =
                (f2lo(b0) + f2hi(b0)) + (f2lo(b1) + f2hi(b1));
        }
    }
    __syncthreads();

    // ---- gather + stream per g ----
    const unsigned FULL = 0xffffffffu;
    #pragma unroll
    for (int g = 0; g < G; g++) {
        const int tq = g ? tqb : tqa;
        int i0 = t4i.x - tq; i0 = i0 < -16 ? -16 : (i0 > 16 ? 16 : i0); i0 += 16;
        int i1 = t4i.y - tq; i1 = i1 < -16 ? -16 : (i1 > 16 ? 16 : i1); i1 += 16;
        int i2 = t4i.z - tq; i2 = i2 < -16 ? -16 : (i2 > 16 ? 16 : i2); i2 += 16;
        int i3 = t4i.w - tq; i3 = i3 < -16 ? -16 : (i3 > 16 ? 16 : i3); i3 += 16;

        const int  ilead = __shfl_sync(FULL, i0, 0);
        const bool uniw  = __all_sync(FULL,
            (i0 == i1) && (i1 == i2) && (i2 == i3) && (i0 == ilead));

        const float* Sg = &S2[g * H * PS];
        if (uniw) {
            #pragma unroll
            for (int hh = 0; hh < H; hh++) {
                float s = Sg[hh * PS + ilead];
                float4 v = make_float4(s, s, s, s);
                float4* o4 = reinterpret_cast<float4*>(
                    out + ((((size_t)b * H + hh) * LQ + q0 + g) * KLEN));
                __stcs(o4 + tid, v);
            }
        } else {
            #pragma unroll
            for (int hh = 0; hh < H; hh++) {
                const float* row = &Sg[hh * PS];
                float4 v;
                v.x = row[i0];
                v.y = row[i1];
                v.z = row[i2];
                v.w = row[i3];
                float4* o4 = reinterpret_cast<float4*>(
                    out + ((((size_t)b * H + hh) * LQ + q0 + g) * KLEN));
                __stcs(o4 + tid, v);
            }
        }
    }
}

extern "C" void kernel_launch(void* const* d_in, const int* in_sizes, int n_in,
                              void* d_out, int out_size)
{
    const float* q     = (const float*)d_in[0];
    const float* table = (const float*)d_in[1];
    const int*   tids  = (const int*)d_in[2];
    float*       out   = (float*)d_out;

    relpe_fused<<<(B * LQ) / G, 256>>>(q, table, tids, out);
}

// round 15
// speedup vs baseline: 2.0979x; 2.0979x over previous
#include <cuda_runtime.h>
#include <cuda_bf16.h>
#include <stdint.h>

constexpr int B    = 4;
constexpr int H    = 8;
constexpr int LQ   = 1024;
constexpr int DH   = 64;
constexpr int KLEN = 1024;
constexpr int TBL  = 33;     // 2*MAX_REL_POS + 1
constexpr int TP   = 68;     // padded row stride (272B): conflict-free map
constexpr int PS   = 34;     // S2 j-stride
constexpr int TPB  = 4;      // tiles (qpos) per block

__device__ __forceinline__ void ffma2(unsigned long long& acc,
                                      unsigned long long a,
                                      unsigned long long b)
{
    asm("fma.rn.f32x2 %0, %1, %2, %0;" : "+l"(acc) : "l"(a), "l"(b));
}
__device__ __forceinline__ float f2lo(unsigned long long v) {
    return __uint_as_float((unsigned)v);
}
__device__ __forceinline__ float f2hi(unsigned long long v) {
    return __uint_as_float((unsigned)(v >> 32));
}

// ---------------------------------------------------------------------------
// Persistent fused kernel: each block serves 4 consecutive (b,q) tiles.
//  * Table staged ONCE per block (amortized 4x), pad-68 rows.
//  * q slab double-buffered: tile i+1 staged during tile i's store phase;
//    ONE barrier per tile.
//  * S-compute map: h = lane>>2, j = warp*4 + (lane&3):
//      q chunk = 8 rows x 16B @272B stride -> 1 wavefront
//      t chunk = 4 rows x 16B              -> 1 wavefront
//  * Gather: warp-uniform idx fast path; coalesced streaming STG.128.
// ---------------------------------------------------------------------------
__global__ __launch_bounds__(256)
void relpe_fused(const float* __restrict__ q,
                 const float* __restrict__ table,
                 const int* __restrict__ tids,
                 float* __restrict__ out)
{
    __shared__ __align__(16) float tsh[TBL * TP];      // 8.8 KB
    __shared__ __align__(16) float qsh[2][H * TP];     // 4.3 KB
    __shared__ float S2[2][H * PS];                    // 2.2 KB

    const int tid  = threadIdx.x;
    const int lane = tid & 31;
    const int w    = tid >> 5;
    const int h    = lane >> 2;          // 0..7
    const int jj   = w * 4 + (lane & 3); // 0..31

    const int t0 = blockIdx.x * TPB;     // first tile
    const int b  = t0 >> 10;             // same b for all 4 tiles (4 | 1024)
    const int q0 = t0 & (LQ - 1);

    // ---- stage table once: 528 float4, coalesced ----
    {
        const float4* t4 = reinterpret_cast<const float4*>(table);
        for (int i = tid; i < (TBL * DH) / 4; i += 256) {
            float4 v = t4[i];
            *reinterpret_cast<float4*>(&tsh[(i >> 4) * TP + 4 * (i & 15)]) = v;
        }
    }
    // ---- stage q slab for tile 0 ----
    if (tid < 128) {
        int hh = tid >> 4, c4 = tid & 15;
        float4 v = reinterpret_cast<const float4*>(
            q + (((size_t)b * H + hh) * LQ + q0) * DH)[c4];
        *reinterpret_cast<float4*>(&qsh[0][hh * TP + 4 * c4]) = v;
    }

    // ---- time ids: window + 4 tq, loaded once ----
    int4 t4i = reinterpret_cast<const int4*>(tids + (size_t)b * KLEN)[tid];
    int4 tq4 = *reinterpret_cast<const int4*>(tids + (size_t)b * KLEN + q0);
    int tqs[TPB] = {tq4.x, tq4.y, tq4.z, tq4.w};

    __syncthreads();

    const unsigned FULL = 0xffffffffu;

    #pragma unroll
    for (int it = 0; it < TPB; it++) {
        const int buf = it & 1;

        // ---- compute S[buf] ----
        {
            const ulonglong2* qrow =
                reinterpret_cast<const ulonglong2*>(&qsh[buf][h * TP]);
            const ulonglong2* trow =
                reinterpret_cast<const ulonglong2*>(&tsh[jj * TP]);
            unsigned long long a0 = 0ull, a1 = 0ull;
            #pragma unroll
            for (int c = 0; c < 16; c++) {
                ulonglong2 qa = qrow[c];
                ulonglong2 ta = trow[c];
                ffma2(a0, qa.x, ta.x);
                ffma2(a1, qa.y, ta.y);
            }
            S2[buf][h * PS + jj] =
                (f2lo(a0) + f2hi(a0)) + (f2lo(a1) + f2hi(a1));

            if (tid < H) {   // tail j = 32
                const ulonglong2* qr2 =
                    reinterpret_cast<const ulonglong2*>(&qsh[buf][tid * TP]);
                const ulonglong2* tr2 =
                    reinterpret_cast<const ulonglong2*>(&tsh[32 * TP]);
                unsigned long long b0 = 0ull, b1 = 0ull;
                #pragma unroll
                for (int c = 0; c < 16; c++) {
                    ulonglong2 qa = qr2[c];
                    ulonglong2 ta = tr2[c];
                    ffma2(b0, qa.x, ta.x);
                    ffma2(b1, qa.y, ta.y);
                }
                S2[buf][tid * PS + 32] =
                    (f2lo(b0) + f2hi(b0)) + (f2lo(b1) + f2hi(b1));
            }
        }

        // ---- stage next q slab into other buffer (overlaps compute/store) ----
        if (it < TPB - 1 && tid < 128) {
            int hh = tid >> 4, c4 = tid & 15;
            float4 v = reinterpret_cast<const float4*>(
                q + (((size_t)b * H + hh) * LQ + q0 + it + 1) * DH)[c4];
            *reinterpret_cast<float4*>(&qsh[buf ^ 1][hh * TP + 4 * c4]) = v;
        }

        __syncthreads();   // S2[buf] complete; qsh[buf^1] staged

        // ---- gather + stream tile it ----
        {
            const int tq = tqs[it];
            int i0 = t4i.x - tq; i0 = i0 < -16 ? -16 : (i0 > 16 ? 16 : i0); i0 += 16;
            int i1 = t4i.y - tq; i1 = i1 < -16 ? -16 : (i1 > 16 ? 16 : i1); i1 += 16;
            int i2 = t4i.z - tq; i2 = i2 < -16 ? -16 : (i2 > 16 ? 16 : i2); i2 += 16;
            int i3 = t4i.w - tq; i3 = i3 < -16 ? -16 : (i3 > 16 ? 16 : i3); i3 += 16;

            const int  ilead = __shfl_sync(FULL, i0, 0);
            const bool uniw  = __all_sync(FULL,
                (i0 == i1) && (i1 == i2) && (i2 == i3) && (i0 == ilead));

            const float* Sg = S2[buf];
            if (uniw) {
                #pragma unroll
                for (int hh = 0; hh < H; hh++) {
                    float s = Sg[hh * PS + ilead];
                    float4 v = make_float4(s, s, s, s);
                    float4* o4 = reinterpret_cast<float4*>(
                        out + ((((size_t)b * H + hh) * LQ + q0 + it) * KLEN));
                    __stcs(o4 + tid, v);
                }
            } else {
                #pragma unroll
                for (int hh = 0; hh < H; hh++) {
                    const float* row = &Sg[hh * PS];
                    float4 v;
                    v.x = row[i0];
                    v.y = row[i1];
                    v.z = row[i2];
                    v.w = row[i3];
                    float4* o4 = reinterpret_cast<float4*>(
                        out + ((((size_t)b * H + hh) * LQ + q0 + it) * KLEN));
                    __stcs(o4 + tid, v);
                }
            }
        }
        // no barrier here: next compute writes S2[buf^1] and reads qsh[buf^1];
        // stores above read S2[buf] which is rewritten only after the NEXT
        // iteration's barrier.
    }
}

extern "C" void kernel_launch(void* const* d_in, const int* in_sizes, int n_in,
                              void* d_out, int out_size)
{
    const float* q     = (const float*)d_in[0];
    const float* table = (const float*)d_in[1];
    const int*   tids  = (const int*)d_in[2];
    float*       out   = (float*)d_out;

    relpe_fused<<<(B * LQ) / TPB, 256>>>(q, table, tids, out);
}